// round 12
// baseline (speedup 1.0000x reference)
#include <cuda_runtime.h>
#include <cuda_bf16.h>

#define Bb 256
#define Tt 1024
#define INF 128
#define Hh 10
#define OUTD 128
#define BT (Bb*Tt)

// Scratch (no cudaMalloc allowed): device global
__device__ float g_xp0[(size_t)BT * Hh];   // [BT][10]

// ---------------------------------------------------------------------------
// Kernel 1: xp0 = x @ W_ih0^T + b  (frozen R6 version, 59.3us known)
// ---------------------------------------------------------------------------
__global__ __launch_bounds__(128) void k1_inproj(
    const float* __restrict__ x,
    const float* __restrict__ W_ih0,
    const float* __restrict__ b_ih0,
    const float* __restrict__ b_hh0)
{
    __shared__ float xs[128 * 129];
    __shared__ float4 Wq[128][3];
    __shared__ float bs[16];
    int tid = threadIdx.x;
    for (int i = tid; i < 128 * 3; i += 128) {
        int f = i / 3, g = i % 3;
        float4 v;
        v.x = (4*g+0 < Hh) ? W_ih0[(4*g+0)*128 + f] : 0.f;
        v.y = (4*g+1 < Hh) ? W_ih0[(4*g+1)*128 + f] : 0.f;
        v.z = (4*g+2 < Hh) ? W_ih0[(4*g+2)*128 + f] : 0.f;
        v.w = (4*g+3 < Hh) ? W_ih0[(4*g+3)*128 + f] : 0.f;
        Wq[f][g] = v;
    }
    if (tid < Hh) bs[tid] = b_ih0[tid] + b_hh0[tid];

    const float* xrow = x + (size_t)blockIdx.x * 128 * 128;
    #pragma unroll 16
    for (int i = tid; i < 128 * 128; i += 128) {
        xs[(i >> 7) * 129 + (i & 127)] = xrow[i];
    }
    __syncthreads();

    float acc[Hh];
    #pragma unroll
    for (int h = 0; h < Hh; h++) acc[h] = bs[h];

    const float* xr = xs + tid * 129;
    #pragma unroll 8
    for (int f = 0; f < 128; f++) {
        float xv = xr[f];
        float4 wa = Wq[f][0], wb = Wq[f][1], wc = Wq[f][2];
        acc[0] = fmaf(xv, wa.x, acc[0]);
        acc[1] = fmaf(xv, wa.y, acc[1]);
        acc[2] = fmaf(xv, wa.z, acc[2]);
        acc[3] = fmaf(xv, wa.w, acc[3]);
        acc[4] = fmaf(xv, wb.x, acc[4]);
        acc[5] = fmaf(xv, wb.y, acc[5]);
        acc[6] = fmaf(xv, wb.z, acc[6]);
        acc[7] = fmaf(xv, wb.w, acc[7]);
        acc[8] = fmaf(xv, wc.x, acc[8]);
        acc[9] = fmaf(xv, wc.y, acc[9]);
    }
    __syncthreads();
    float* os = xs;                          // [128][12]
    #pragma unroll
    for (int h = 0; h < Hh; h++) os[tid * 12 + h] = acc[h];
    __syncthreads();

    float4* g4 = (float4*)(g_xp0 + (size_t)blockIdx.x * 128 * Hh);
    for (int i = tid; i < 320; i += 128) {
        int e = i * 4;
        float4 v;
        v.x = os[(e    ) / 10 * 12 + (e    ) % 10];
        v.y = os[(e + 1) / 10 * 12 + (e + 1) % 10];
        v.z = os[(e + 2) / 10 * 12 + (e + 2) % 10];
        v.w = os[(e + 3) / 10 * 12 + (e + 3) % 10];
        g4[i] = v;
    }
}

// ---------------------------------------------------------------------------
// Kernel 2: fully fused scan + head. One block = one batch, 4 warps:
//   w0: layer-0 producer  -> h0buf ring (R6 proven: shfl state, group publish)
//   w1: layer-1 consumer  -> h1buf ring (R6 proven; STS instead of STG)
//   w2,w3: head+softmax, trailing group-granularly, alternate t's,
//          write softmax rows straight to out (k3 + g_out2 DELETED).
// ---------------------------------------------------------------------------
__global__ __launch_bounds__(128) void k2_scan(
    const float* __restrict__ W_hh0,
    const float* __restrict__ W_ih1,
    const float* __restrict__ W_hh1,
    const float* __restrict__ b_ih1,
    const float* __restrict__ b_hh1,
    const float* __restrict__ W_lin,
    const float* __restrict__ b_lin,
    float* __restrict__ out)
{
    extern __shared__ float smem[];          // h0buf[1024][12] ++ h1buf[1024][12]
    float* h0buf = smem;
    float* h1buf = smem + Tt * 12;
    __shared__ int prog0_s, prog1_s;
    const unsigned FULL = 0xffffffffu;
    int tid  = threadIdx.x;
    int wid  = tid >> 5;
    int lane = tid & 31;
    int j    = lane < Hh ? lane : Hh - 1;
    int batch = blockIdx.x;
    volatile int* prog0 = &prog0_s;
    volatile int* prog1 = &prog1_s;

    if (tid == 0) { prog0_s = 0; prog1_s = 0; }
    __syncthreads();

    float* hid = out + (size_t)BT * OUTD;    // hidden: [2][B][H]

    if (wid == 0) {
        // ---------------- producer: layer 0 ----------------
        float w0r[Hh];
        #pragma unroll
        for (int k = 0; k < Hh; k++) w0r[k] = W_hh0[j * Hh + k];

        const float* xp = g_xp0 + (size_t)batch * Tt * Hh;
        float v0[Hh];
        #pragma unroll
        for (int k = 0; k < Hh; k++) v0[k] = 0.f;

        float xa[8], xb[8];
        #pragma unroll
        for (int d = 0; d < 8; d++) xa[d] = xp[d * Hh + j];

        float h0n = 0.f;
        for (int tb = 0; tb < Tt; tb += 8) {
            if (tb + 8 < Tt) {
                #pragma unroll
                for (int d = 0; d < 8; d++) xb[d] = xp[(tb + 8 + d) * Hh + j];
            }
            #pragma unroll
            for (int d = 0; d < 8; d++) {
                float a0 = xa[d], a1 = 0.f, a2 = 0.f, a3 = 0.f;
                a0 = fmaf(w0r[0], v0[0], a0);
                a1 = fmaf(w0r[1], v0[1], a1);
                a2 = fmaf(w0r[2], v0[2], a2);
                a3 = fmaf(w0r[3], v0[3], a3);
                a0 = fmaf(w0r[4], v0[4], a0);
                a1 = fmaf(w0r[5], v0[5], a1);
                a2 = fmaf(w0r[6], v0[6], a2);
                a3 = fmaf(w0r[7], v0[7], a3);
                a0 = fmaf(w0r[8], v0[8], a0);
                a1 = fmaf(w0r[9], v0[9], a1);
                h0n = fmaxf((a0 + a1) + (a2 + a3), 0.f);
                if (lane < Hh) h0buf[(tb + d) * 12 + lane] = h0n;
                #pragma unroll
                for (int k = 0; k < Hh; k++) v0[k] = __shfl_sync(FULL, h0n, k);
            }
            __threadfence_block();
            if (lane == 0) *prog0 = tb + 8;
            #pragma unroll
            for (int d = 0; d < 8; d++) xa[d] = xb[d];
        }
        if (lane < Hh) hid[batch * Hh + lane] = h0n;       // h0[T-1]
    } else if (wid == 1) {
        // ---------------- consumer: layer 1 ----------------
        float wi1r[Hh], w1r[Hh];
        #pragma unroll
        for (int k = 0; k < Hh; k++) {
            wi1r[k] = W_ih1[j * Hh + k];
            w1r[k]  = W_hh1[j * Hh + k];
        }
        float bias1 = b_ih1[j] + b_hh1[j];

        float v1[Hh];
        #pragma unroll
        for (int k = 0; k < Hh; k++) v1[k] = 0.f;
        float h1n = 0.f;

        int seen = 0;
        while ((seen = *prog0) < 8) { }
        __threadfence_block();
        const float4* rb = (const float4*)h0buf;
        float4 c0 = rb[0], c1 = rb[1], c2 = rb[2];

        for (int tb = 0; tb < Tt; tb += 8) {
            #pragma unroll
            for (int d = 0; d < 8; d++) {
                int t = tb + d;
                float4 n0, n1, n2;
                if (d < 7) {                 // compile-time prefetch
                    const float4* rn = (const float4*)(h0buf + (t + 1) * 12);
                    n0 = rn[0]; n1 = rn[1]; n2 = rn[2];
                }
                float r0 = bias1, r1 = 0.f, r2 = 0.f, r3 = 0.f;
                r0 = fmaf(wi1r[0], c0.x, r0);
                r1 = fmaf(wi1r[1], c0.y, r1);
                r2 = fmaf(wi1r[2], c0.z, r2);
                r3 = fmaf(wi1r[3], c0.w, r3);
                r0 = fmaf(wi1r[4], c1.x, r0);
                r1 = fmaf(wi1r[5], c1.y, r1);
                r2 = fmaf(wi1r[6], c1.z, r2);
                r3 = fmaf(wi1r[7], c1.w, r3);
                r0 = fmaf(wi1r[8], c2.x, r0);
                r1 = fmaf(wi1r[9], c2.y, r1);
                r0 = fmaf(w1r[0], v1[0], r0);
                r1 = fmaf(w1r[1], v1[1], r1);
                r2 = fmaf(w1r[2], v1[2], r2);
                r3 = fmaf(w1r[3], v1[3], r3);
                r0 = fmaf(w1r[4], v1[4], r0);
                r1 = fmaf(w1r[5], v1[5], r1);
                r2 = fmaf(w1r[6], v1[6], r2);
                r3 = fmaf(w1r[7], v1[7], r3);
                r0 = fmaf(w1r[8], v1[8], r0);
                r1 = fmaf(w1r[9], v1[9], r1);
                h1n = fmaxf((r0 + r1) + (r2 + r3), 0.f);
                if (lane < Hh) h1buf[t * 12 + lane] = h1n;   // STS, not STG
                #pragma unroll
                for (int k = 0; k < Hh; k++) v1[k] = __shfl_sync(FULL, h1n, k);
                if (d < 7) { c0 = n0; c1 = n1; c2 = n2; }
            }
            __threadfence_block();
            if (lane == 0) *prog1 = tb + 8;                  // publish h1 group
            if (tb + 8 < Tt) {
                int need = tb + 16;
                if (seen < need) {
                    while ((seen = *prog0) < need) { }
                    __threadfence_block();
                }
                const float4* rn = (const float4*)(h0buf + (tb + 8) * 12);
                c0 = rn[0]; c1 = rn[1]; c2 = rn[2];
            }
        }
        if (lane < Hh) hid[Bb * Hh + batch * Hh + lane] = h1n;   // h1[T-1]
    } else {
        // ---------------- head warps (wid 2,3): logits + softmax ----------
        int hw = wid - 2;                    // 0 or 1: takes t with (t&1)==hw
        float wl[4][Hh], bb[4];
        #pragma unroll
        for (int c = 0; c < 4; c++) {
            int o = 4 * lane + c;
            bb[c] = b_lin[o];
            #pragma unroll
            for (int k = 0; k < Hh; k++) wl[c][k] = W_lin[o * Hh + k];
        }
        float* orow_base = out + (size_t)batch * Tt * OUTD;

        int seen1 = 0;
        for (int tb = 0; tb < Tt; tb += 8) {
            int need = tb + 8;
            if (seen1 < need) {
                while ((seen1 = *prog1) < need) { }
                __threadfence_block();
            }
            #pragma unroll
            for (int d = 0; d < 8; d++) {
                if ((d & 1) != hw) continue;     // compile-time alternation
                int t = tb + d;
                const float4* hb = (const float4*)(h1buf + t * 12);
                float4 p0 = hb[0], p1 = hb[1], p2 = hb[2];
                float hk[Hh] = {p0.x, p0.y, p0.z, p0.w, p1.x,
                                p1.y, p1.z, p1.w, p2.x, p2.y};
                float acc[4];
                #pragma unroll
                for (int c = 0; c < 4; c++) {
                    acc[c] = bb[c];
                    #pragma unroll
                    for (int k = 0; k < Hh; k++)
                        acc[c] = fmaf(hk[k], wl[c][k], acc[c]);
                }
                float m = fmaxf(fmaxf(acc[0], acc[1]), fmaxf(acc[2], acc[3]));
                #pragma unroll
                for (int s = 16; s > 0; s >>= 1)
                    m = fmaxf(m, __shfl_xor_sync(FULL, m, s));
                float e0 = __expf(acc[0] - m), e1 = __expf(acc[1] - m);
                float e2 = __expf(acc[2] - m), e3 = __expf(acc[3] - m);
                float s = e0 + e1 + e2 + e3;
                #pragma unroll
                for (int sh = 16; sh > 0; sh >>= 1)
                    s += __shfl_xor_sync(FULL, s, sh);
                float r = __frcp_rn(s);
                float4 res = make_float4(e0 * r, e1 * r, e2 * r, e3 * r);
                ((float4*)(orow_base + (size_t)t * OUTD))[lane] = res;
            }
        }
    }
}

// ---------------------------------------------------------------------------
extern "C" void kernel_launch(void* const* d_in, const int* in_sizes, int n_in,
                              void* d_out, int out_size)
{
    const float* x      = (const float*)d_in[0];
    const float* W_ih0  = (const float*)d_in[1];
    const float* W_hh0  = (const float*)d_in[2];
    const float* b_ih0  = (const float*)d_in[3];
    const float* b_hh0  = (const float*)d_in[4];
    const float* W_ih1  = (const float*)d_in[5];
    const float* W_hh1  = (const float*)d_in[6];
    const float* b_ih1  = (const float*)d_in[7];
    const float* b_hh1  = (const float*)d_in[8];
    const float* W_lin  = (const float*)d_in[9];
    const float* b_lin  = (const float*)d_in[10];
    float* out = (float*)d_out;

    const int k2_smem = 2 * Tt * 12 * sizeof(float);   // 96KB
    cudaFuncSetAttribute(k2_scan, cudaFuncAttributeMaxDynamicSharedMemorySize,
                         k2_smem);

    k1_inproj<<<2048, 128>>>(x, W_ih0, b_ih0, b_hh0);
    k2_scan<<<Bb, 128, k2_smem>>>(W_hh0, W_ih1, W_hh1, b_ih1, b_hh1,
                                  W_lin, b_lin, out);
}

// round 13
// speedup vs baseline: 1.0010x; 1.0010x over previous
#include <cuda_runtime.h>
#include <cuda_bf16.h>

#define Bb 256
#define Tt 1024
#define INF 128
#define Hh 10
#define OUTD 128
#define BT (Bb*Tt)

// Scratch (no cudaMalloc allowed): device global
__device__ float g_xp0[(size_t)BT * Hh];   // [BT][10]

// ---------------------------------------------------------------------------
// Kernel 1: xp0 = x @ W_ih0^T + b  (frozen R6 version, 59.3us known)
// ---------------------------------------------------------------------------
__global__ __launch_bounds__(128) void k1_inproj(
    const float* __restrict__ x,
    const float* __restrict__ W_ih0,
    const float* __restrict__ b_ih0,
    const float* __restrict__ b_hh0)
{
    __shared__ float xs[128 * 129];
    __shared__ float4 Wq[128][3];
    __shared__ float bs[16];
    int tid = threadIdx.x;
    for (int i = tid; i < 128 * 3; i += 128) {
        int f = i / 3, g = i % 3;
        float4 v;
        v.x = (4*g+0 < Hh) ? W_ih0[(4*g+0)*128 + f] : 0.f;
        v.y = (4*g+1 < Hh) ? W_ih0[(4*g+1)*128 + f] : 0.f;
        v.z = (4*g+2 < Hh) ? W_ih0[(4*g+2)*128 + f] : 0.f;
        v.w = (4*g+3 < Hh) ? W_ih0[(4*g+3)*128 + f] : 0.f;
        Wq[f][g] = v;
    }
    if (tid < Hh) bs[tid] = b_ih0[tid] + b_hh0[tid];

    const float* xrow = x + (size_t)blockIdx.x * 128 * 128;
    #pragma unroll 16
    for (int i = tid; i < 128 * 128; i += 128) {
        xs[(i >> 7) * 129 + (i & 127)] = xrow[i];
    }
    __syncthreads();

    float acc[Hh];
    #pragma unroll
    for (int h = 0; h < Hh; h++) acc[h] = bs[h];

    const float* xr = xs + tid * 129;
    #pragma unroll 8
    for (int f = 0; f < 128; f++) {
        float xv = xr[f];
        float4 wa = Wq[f][0], wb = Wq[f][1], wc = Wq[f][2];
        acc[0] = fmaf(xv, wa.x, acc[0]);
        acc[1] = fmaf(xv, wa.y, acc[1]);
        acc[2] = fmaf(xv, wa.z, acc[2]);
        acc[3] = fmaf(xv, wa.w, acc[3]);
        acc[4] = fmaf(xv, wb.x, acc[4]);
        acc[5] = fmaf(xv, wb.y, acc[5]);
        acc[6] = fmaf(xv, wb.z, acc[6]);
        acc[7] = fmaf(xv, wb.w, acc[7]);
        acc[8] = fmaf(xv, wc.x, acc[8]);
        acc[9] = fmaf(xv, wc.y, acc[9]);
    }
    __syncthreads();
    float* os = xs;                          // [128][12]
    #pragma unroll
    for (int h = 0; h < Hh; h++) os[tid * 12 + h] = acc[h];
    __syncthreads();

    float4* g4 = (float4*)(g_xp0 + (size_t)blockIdx.x * 128 * Hh);
    for (int i = tid; i < 320; i += 128) {
        int e = i * 4;
        float4 v;
        v.x = os[(e    ) / 10 * 12 + (e    ) % 10];
        v.y = os[(e + 1) / 10 * 12 + (e + 1) % 10];
        v.z = os[(e + 2) / 10 * 12 + (e + 2) % 10];
        v.w = os[(e + 3) / 10 * 12 + (e + 3) % 10];
        g4[i] = v;
    }
}

// ---------------------------------------------------------------------------
// Kernel 2: fully fused scan + head. One block = one batch, 4 warps:
//   w0: layer-0 producer  -> h0buf ring (R6 proven: shfl state, group publish)
//   w1: layer-1 consumer  -> h1buf ring (R6 proven; STS instead of STG)
//   w2,w3: head+softmax, trailing group-granularly, alternate t's,
//          write softmax rows straight to out (k3 + g_out2 DELETED).
// ---------------------------------------------------------------------------
__global__ __launch_bounds__(128) void k2_scan(
    const float* __restrict__ W_hh0,
    const float* __restrict__ W_ih1,
    const float* __restrict__ W_hh1,
    const float* __restrict__ b_ih1,
    const float* __restrict__ b_hh1,
    const float* __restrict__ W_lin,
    const float* __restrict__ b_lin,
    float* __restrict__ out)
{
    extern __shared__ float smem[];          // h0buf[1024][12] ++ h1buf[1024][12]
    float* h0buf = smem;
    float* h1buf = smem + Tt * 12;
    __shared__ int prog0_s, prog1_s;
    const unsigned FULL = 0xffffffffu;
    int tid  = threadIdx.x;
    int wid  = tid >> 5;
    int lane = tid & 31;
    int j    = lane < Hh ? lane : Hh - 1;
    int batch = blockIdx.x;
    volatile int* prog0 = &prog0_s;
    volatile int* prog1 = &prog1_s;

    if (tid == 0) { prog0_s = 0; prog1_s = 0; }
    __syncthreads();

    float* hid = out + (size_t)BT * OUTD;    // hidden: [2][B][H]

    if (wid == 0) {
        // ---------------- producer: layer 0 ----------------
        float w0r[Hh];
        #pragma unroll
        for (int k = 0; k < Hh; k++) w0r[k] = W_hh0[j * Hh + k];

        const float* xp = g_xp0 + (size_t)batch * Tt * Hh;
        float v0[Hh];
        #pragma unroll
        for (int k = 0; k < Hh; k++) v0[k] = 0.f;

        float xa[8], xb[8];
        #pragma unroll
        for (int d = 0; d < 8; d++) xa[d] = xp[d * Hh + j];

        float h0n = 0.f;
        for (int tb = 0; tb < Tt; tb += 8) {
            if (tb + 8 < Tt) {
                #pragma unroll
                for (int d = 0; d < 8; d++) xb[d] = xp[(tb + 8 + d) * Hh + j];
            }
            #pragma unroll
            for (int d = 0; d < 8; d++) {
                float a0 = xa[d], a1 = 0.f, a2 = 0.f, a3 = 0.f;
                a0 = fmaf(w0r[0], v0[0], a0);
                a1 = fmaf(w0r[1], v0[1], a1);
                a2 = fmaf(w0r[2], v0[2], a2);
                a3 = fmaf(w0r[3], v0[3], a3);
                a0 = fmaf(w0r[4], v0[4], a0);
                a1 = fmaf(w0r[5], v0[5], a1);
                a2 = fmaf(w0r[6], v0[6], a2);
                a3 = fmaf(w0r[7], v0[7], a3);
                a0 = fmaf(w0r[8], v0[8], a0);
                a1 = fmaf(w0r[9], v0[9], a1);
                h0n = fmaxf((a0 + a1) + (a2 + a3), 0.f);
                if (lane < Hh) h0buf[(tb + d) * 12 + lane] = h0n;
                #pragma unroll
                for (int k = 0; k < Hh; k++) v0[k] = __shfl_sync(FULL, h0n, k);
            }
            __threadfence_block();
            if (lane == 0) *prog0 = tb + 8;
            #pragma unroll
            for (int d = 0; d < 8; d++) xa[d] = xb[d];
        }
        if (lane < Hh) hid[batch * Hh + lane] = h0n;       // h0[T-1]
    } else if (wid == 1) {
        // ---------------- consumer: layer 1 ----------------
        float wi1r[Hh], w1r[Hh];
        #pragma unroll
        for (int k = 0; k < Hh; k++) {
            wi1r[k] = W_ih1[j * Hh + k];
            w1r[k]  = W_hh1[j * Hh + k];
        }
        float bias1 = b_ih1[j] + b_hh1[j];

        float v1[Hh];
        #pragma unroll
        for (int k = 0; k < Hh; k++) v1[k] = 0.f;
        float h1n = 0.f;

        int seen = 0;
        while ((seen = *prog0) < 8) { }
        __threadfence_block();
        const float4* rb = (const float4*)h0buf;
        float4 c0 = rb[0], c1 = rb[1], c2 = rb[2];

        for (int tb = 0; tb < Tt; tb += 8) {
            #pragma unroll
            for (int d = 0; d < 8; d++) {
                int t = tb + d;
                float4 n0, n1, n2;
                if (d < 7) {                 // compile-time prefetch
                    const float4* rn = (const float4*)(h0buf + (t + 1) * 12);
                    n0 = rn[0]; n1 = rn[1]; n2 = rn[2];
                }
                float r0 = bias1, r1 = 0.f, r2 = 0.f, r3 = 0.f;
                r0 = fmaf(wi1r[0], c0.x, r0);
                r1 = fmaf(wi1r[1], c0.y, r1);
                r2 = fmaf(wi1r[2], c0.z, r2);
                r3 = fmaf(wi1r[3], c0.w, r3);
                r0 = fmaf(wi1r[4], c1.x, r0);
                r1 = fmaf(wi1r[5], c1.y, r1);
                r2 = fmaf(wi1r[6], c1.z, r2);
                r3 = fmaf(wi1r[7], c1.w, r3);
                r0 = fmaf(wi1r[8], c2.x, r0);
                r1 = fmaf(wi1r[9], c2.y, r1);
                r0 = fmaf(w1r[0], v1[0], r0);
                r1 = fmaf(w1r[1], v1[1], r1);
                r2 = fmaf(w1r[2], v1[2], r2);
                r3 = fmaf(w1r[3], v1[3], r3);
                r0 = fmaf(w1r[4], v1[4], r0);
                r1 = fmaf(w1r[5], v1[5], r1);
                r2 = fmaf(w1r[6], v1[6], r2);
                r3 = fmaf(w1r[7], v1[7], r3);
                r0 = fmaf(w1r[8], v1[8], r0);
                r1 = fmaf(w1r[9], v1[9], r1);
                h1n = fmaxf((r0 + r1) + (r2 + r3), 0.f);
                if (lane < Hh) h1buf[t * 12 + lane] = h1n;   // STS, not STG
                #pragma unroll
                for (int k = 0; k < Hh; k++) v1[k] = __shfl_sync(FULL, h1n, k);
                if (d < 7) { c0 = n0; c1 = n1; c2 = n2; }
            }
            __threadfence_block();
            if (lane == 0) *prog1 = tb + 8;                  // publish h1 group
            if (tb + 8 < Tt) {
                int need = tb + 16;
                if (seen < need) {
                    while ((seen = *prog0) < need) { }
                    __threadfence_block();
                }
                const float4* rn = (const float4*)(h0buf + (tb + 8) * 12);
                c0 = rn[0]; c1 = rn[1]; c2 = rn[2];
            }
        }
        if (lane < Hh) hid[Bb * Hh + batch * Hh + lane] = h1n;   // h1[T-1]
    } else {
        // ---------------- head warps (wid 2,3): logits + softmax ----------
        int hw = wid - 2;                    // 0 or 1: takes t with (t&1)==hw
        float wl[4][Hh], bb[4];
        #pragma unroll
        for (int c = 0; c < 4; c++) {
            int o = 4 * lane + c;
            bb[c] = b_lin[o];
            #pragma unroll
            for (int k = 0; k < Hh; k++) wl[c][k] = W_lin[o * Hh + k];
        }
        float* orow_base = out + (size_t)batch * Tt * OUTD;

        int seen1 = 0;
        for (int tb = 0; tb < Tt; tb += 8) {
            int need = tb + 8;
            if (seen1 < need) {
                while ((seen1 = *prog1) < need) { }
                __threadfence_block();
            }
            #pragma unroll
            for (int d = 0; d < 8; d++) {
                if ((d & 1) != hw) continue;     // compile-time alternation
                int t = tb + d;
                const float4* hb = (const float4*)(h1buf + t * 12);
                float4 p0 = hb[0], p1 = hb[1], p2 = hb[2];
                float hk[Hh] = {p0.x, p0.y, p0.z, p0.w, p1.x,
                                p1.y, p1.z, p1.w, p2.x, p2.y};
                float acc[4];
                #pragma unroll
                for (int c = 0; c < 4; c++) {
                    acc[c] = bb[c];
                    #pragma unroll
                    for (int k = 0; k < Hh; k++)
                        acc[c] = fmaf(hk[k], wl[c][k], acc[c]);
                }
                float m = fmaxf(fmaxf(acc[0], acc[1]), fmaxf(acc[2], acc[3]));
                #pragma unroll
                for (int s = 16; s > 0; s >>= 1)
                    m = fmaxf(m, __shfl_xor_sync(FULL, m, s));
                float e0 = __expf(acc[0] - m), e1 = __expf(acc[1] - m);
                float e2 = __expf(acc[2] - m), e3 = __expf(acc[3] - m);
                float s = e0 + e1 + e2 + e3;
                #pragma unroll
                for (int sh = 16; sh > 0; sh >>= 1)
                    s += __shfl_xor_sync(FULL, s, sh);
                float r = __frcp_rn(s);
                float4 res = make_float4(e0 * r, e1 * r, e2 * r, e3 * r);
                ((float4*)(orow_base + (size_t)t * OUTD))[lane] = res;
            }
        }
    }
}

// ---------------------------------------------------------------------------
extern "C" void kernel_launch(void* const* d_in, const int* in_sizes, int n_in,
                              void* d_out, int out_size)
{
    const float* x      = (const float*)d_in[0];
    const float* W_ih0  = (const float*)d_in[1];
    const float* W_hh0  = (const float*)d_in[2];
    const float* b_ih0  = (const float*)d_in[3];
    const float* b_hh0  = (const float*)d_in[4];
    const float* W_ih1  = (const float*)d_in[5];
    const float* W_hh1  = (const float*)d_in[6];
    const float* b_ih1  = (const float*)d_in[7];
    const float* b_hh1  = (const float*)d_in[8];
    const float* W_lin  = (const float*)d_in[9];
    const float* b_lin  = (const float*)d_in[10];
    float* out = (float*)d_out;

    const int k2_smem = 2 * Tt * 12 * sizeof(float);   // 96KB
    cudaFuncSetAttribute(k2_scan, cudaFuncAttributeMaxDynamicSharedMemorySize,
                         k2_smem);

    k1_inproj<<<2048, 128>>>(x, W_ih0, b_ih0, b_hh0);
    k2_scan<<<Bb, 128, k2_smem>>>(W_hh0, W_ih1, W_hh1, b_ih1, b_hh1,
                                  W_lin, b_lin, out);
}

// round 14
// speedup vs baseline: 1.1912x; 1.1901x over previous
#include <cuda_runtime.h>
#include <cuda_bf16.h>

#define Bb 256
#define Tt 1024
#define INF 128
#define Hh 10
#define OUTD 128
#define BT (Bb*Tt)

// Scratch (no cudaMalloc allowed): device globals
__device__ float g_xp0[(size_t)BT * Hh];   // [BT][10]
__device__ float g_out2[(size_t)BT * Hh];  // [BT][10]

// ---------------------------------------------------------------------------
// Kernel 1: xp0 = x @ W_ih0^T + b  (frozen R6 version, 59.3us known)
// ---------------------------------------------------------------------------
__global__ __launch_bounds__(128) void k1_inproj(
    const float* __restrict__ x,
    const float* __restrict__ W_ih0,
    const float* __restrict__ b_ih0,
    const float* __restrict__ b_hh0)
{
    __shared__ float xs[128 * 129];
    __shared__ float4 Wq[128][3];
    __shared__ float bs[16];
    int tid = threadIdx.x;
    for (int i = tid; i < 128 * 3; i += 128) {
        int f = i / 3, g = i % 3;
        float4 v;
        v.x = (4*g+0 < Hh) ? W_ih0[(4*g+0)*128 + f] : 0.f;
        v.y = (4*g+1 < Hh) ? W_ih0[(4*g+1)*128 + f] : 0.f;
        v.z = (4*g+2 < Hh) ? W_ih0[(4*g+2)*128 + f] : 0.f;
        v.w = (4*g+3 < Hh) ? W_ih0[(4*g+3)*128 + f] : 0.f;
        Wq[f][g] = v;
    }
    if (tid < Hh) bs[tid] = b_ih0[tid] + b_hh0[tid];

    const float* xrow = x + (size_t)blockIdx.x * 128 * 128;
    #pragma unroll 16
    for (int i = tid; i < 128 * 128; i += 128) {
        xs[(i >> 7) * 129 + (i & 127)] = xrow[i];
    }
    __syncthreads();

    float acc[Hh];
    #pragma unroll
    for (int h = 0; h < Hh; h++) acc[h] = bs[h];

    const float* xr = xs + tid * 129;
    #pragma unroll 8
    for (int f = 0; f < 128; f++) {
        float xv = xr[f];
        float4 wa = Wq[f][0], wb = Wq[f][1], wc = Wq[f][2];
        acc[0] = fmaf(xv, wa.x, acc[0]);
        acc[1] = fmaf(xv, wa.y, acc[1]);
        acc[2] = fmaf(xv, wa.z, acc[2]);
        acc[3] = fmaf(xv, wa.w, acc[3]);
        acc[4] = fmaf(xv, wb.x, acc[4]);
        acc[5] = fmaf(xv, wb.y, acc[5]);
        acc[6] = fmaf(xv, wb.z, acc[6]);
        acc[7] = fmaf(xv, wb.w, acc[7]);
        acc[8] = fmaf(xv, wc.x, acc[8]);
        acc[9] = fmaf(xv, wc.y, acc[9]);
    }
    __syncthreads();
    float* os = xs;                          // [128][12]
    #pragma unroll
    for (int h = 0; h < Hh; h++) os[tid * 12 + h] = acc[h];
    __syncthreads();

    float4* g4 = (float4*)(g_xp0 + (size_t)blockIdx.x * 128 * Hh);
    for (int i = tid; i < 320; i += 128) {
        int e = i * 4;
        float4 v;
        v.x = os[(e    ) / 10 * 12 + (e    ) % 10];
        v.y = os[(e + 1) / 10 * 12 + (e + 1) % 10];
        v.z = os[(e + 2) / 10 * 12 + (e + 2) % 10];
        v.w = os[(e + 3) / 10 * 12 + (e + 3) % 10];
        g4[i] = v;
    }
}

// ---------------------------------------------------------------------------
// Kernel 2: warp-specialized scan (R6 proven), re-mapped so the 4 busy warps
// of TWO batches land on the 4 DISTINCT SMSPs of one SM:
//   wid0 = producer(batchA) SMSP0   wid1 = consumer(batchA) SMSP1
//   wid2 = producer(batchB) SMSP2   wid3 = consumer(batchB) SMSP3
// 128 blocks < 148 SMs -> 1 block/SM, every busy warp has a private SMSP.
// ---------------------------------------------------------------------------
__global__ __launch_bounds__(128) void k2_scan(
    const float* __restrict__ W_hh0,
    const float* __restrict__ W_ih1,
    const float* __restrict__ W_hh1,
    const float* __restrict__ b_ih1,
    const float* __restrict__ b_hh1,
    float* __restrict__ dout)
{
    extern __shared__ float smem[];         // bufA[1024][12] ++ bufB[1024][12]
    __shared__ int prog_s[2];
    const unsigned FULL = 0xffffffffu;
    int tid  = threadIdx.x;
    int wid  = tid >> 5;
    int lane = tid & 31;
    int j    = lane < Hh ? lane : Hh - 1;

    if (tid < 2) prog_s[tid] = 0;
    __syncthreads();

    int side   = wid >> 1;                  // 0 = batch A, 1 = batch B
    int role   = wid & 1;                   // 0 = producer, 1 = consumer
    int batch  = blockIdx.x * 2 + side;
    float* buf = smem + side * (Tt * 12);
    volatile int* pprog = &prog_s[side];

    float* hid = dout + (size_t)BT * OUTD;  // hidden: [2][B][H]

    if (role == 0) {
        // ---------------- producer: layer 0 ----------------
        float w0r[Hh];
        #pragma unroll
        for (int k = 0; k < Hh; k++) w0r[k] = W_hh0[j * Hh + k];

        const float* xp = g_xp0 + (size_t)batch * Tt * Hh;
        float v0[Hh];
        #pragma unroll
        for (int k = 0; k < Hh; k++) v0[k] = 0.f;

        float xa[8], xb[8];
        #pragma unroll
        for (int d = 0; d < 8; d++) xa[d] = xp[d * Hh + j];

        float h0n = 0.f;
        for (int tb = 0; tb < Tt; tb += 8) {
            if (tb + 8 < Tt) {
                #pragma unroll
                for (int d = 0; d < 8; d++) xb[d] = xp[(tb + 8 + d) * Hh + j];
            }
            #pragma unroll
            for (int d = 0; d < 8; d++) {
                float a0 = xa[d], a1 = 0.f, a2 = 0.f, a3 = 0.f;
                a0 = fmaf(w0r[0], v0[0], a0);
                a1 = fmaf(w0r[1], v0[1], a1);
                a2 = fmaf(w0r[2], v0[2], a2);
                a3 = fmaf(w0r[3], v0[3], a3);
                a0 = fmaf(w0r[4], v0[4], a0);
                a1 = fmaf(w0r[5], v0[5], a1);
                a2 = fmaf(w0r[6], v0[6], a2);
                a3 = fmaf(w0r[7], v0[7], a3);
                a0 = fmaf(w0r[8], v0[8], a0);
                a1 = fmaf(w0r[9], v0[9], a1);
                h0n = fmaxf((a0 + a1) + (a2 + a3), 0.f);
                if (lane < Hh) buf[(tb + d) * 12 + lane] = h0n;
                #pragma unroll
                for (int k = 0; k < Hh; k++) v0[k] = __shfl_sync(FULL, h0n, k);
            }
            __threadfence_block();
            if (lane == 0) *pprog = tb + 8;          // unconditional publish
            #pragma unroll
            for (int d = 0; d < 8; d++) xa[d] = xb[d];
        }
        if (lane < Hh) hid[batch * Hh + lane] = h0n;      // h0[T-1]
    } else {
        // ---------------- consumer: layer 1 ----------------
        float wi1r[Hh], w1r[Hh];
        #pragma unroll
        for (int k = 0; k < Hh; k++) {
            wi1r[k] = W_ih1[j * Hh + k];
            w1r[k]  = W_hh1[j * Hh + k];
        }
        float bias1 = b_ih1[j] + b_hh1[j];
        float* o2 = g_out2 + (size_t)batch * Tt * Hh;

        float v1[Hh];
        #pragma unroll
        for (int k = 0; k < Hh; k++) v1[k] = 0.f;
        float h1n = 0.f;

        int seen = 0;
        while ((seen = *pprog) < 8) { }     // wait for first group
        __threadfence_block();
        const float4* rb = (const float4*)buf;
        float4 c0 = rb[0], c1 = rb[1], c2 = rb[2];

        for (int tb = 0; tb < Tt; tb += 8) {
            #pragma unroll
            for (int d = 0; d < 8; d++) {
                float4 n0, n1, n2;
                if (d < 7) {                 // compile-time: no runtime branch
                    const float4* rn = (const float4*)(buf + (tb + d + 1) * 12);
                    n0 = rn[0]; n1 = rn[1]; n2 = rn[2];
                }
                float r0 = bias1, r1 = 0.f, r2 = 0.f, r3 = 0.f;
                r0 = fmaf(wi1r[0], c0.x, r0);
                r1 = fmaf(wi1r[1], c0.y, r1);
                r2 = fmaf(wi1r[2], c0.z, r2);
                r3 = fmaf(wi1r[3], c0.w, r3);
                r0 = fmaf(wi1r[4], c1.x, r0);
                r1 = fmaf(wi1r[5], c1.y, r1);
                r2 = fmaf(wi1r[6], c1.z, r2);
                r3 = fmaf(wi1r[7], c1.w, r3);
                r0 = fmaf(wi1r[8], c2.x, r0);
                r1 = fmaf(wi1r[9], c2.y, r1);
                r0 = fmaf(w1r[0], v1[0], r0);
                r1 = fmaf(w1r[1], v1[1], r1);
                r2 = fmaf(w1r[2], v1[2], r2);
                r3 = fmaf(w1r[3], v1[3], r3);
                r0 = fmaf(w1r[4], v1[4], r0);
                r1 = fmaf(w1r[5], v1[5], r1);
                r2 = fmaf(w1r[6], v1[6], r2);
                r3 = fmaf(w1r[7], v1[7], r3);
                r0 = fmaf(w1r[8], v1[8], r0);
                r1 = fmaf(w1r[9], v1[9], r1);
                h1n = fmaxf((r0 + r1) + (r2 + r3), 0.f);
                if (lane < Hh) o2[(size_t)(tb + d) * Hh + lane] = h1n;
                #pragma unroll
                for (int k = 0; k < Hh; k++) v1[k] = __shfl_sync(FULL, h1n, k);
                if (d < 7) { c0 = n0; c1 = n1; c2 = n2; }
            }
            if (tb + 8 < Tt) {               // one poll per group
                int need = tb + 16;
                if (seen < need) {
                    while ((seen = *pprog) < need) { }
                    __threadfence_block();
                }
                const float4* rn = (const float4*)(buf + (tb + 8) * 12);
                c0 = rn[0]; c1 = rn[1]; c2 = rn[2];
            }
        }
        if (lane < Hh) hid[Bb * Hh + batch * Hh + lane] = h1n;   // h1[T-1]
    }
}

// ---------------------------------------------------------------------------
// Kernel 3: logits = out2 @ W_lin^T + b_lin, softmax over 128. (frozen R6)
// ---------------------------------------------------------------------------
__global__ __launch_bounds__(256) void k3_head(
    const float* __restrict__ W_lin,
    const float* __restrict__ b_lin,
    float* __restrict__ out)
{
    const unsigned FULL = 0xffffffffu;
    __shared__ float Wl[OUTD * Hh];
    __shared__ float bl[OUTD];
    int tid = threadIdx.x;
    for (int i = tid; i < OUTD * Hh; i += blockDim.x) Wl[i] = W_lin[i];
    for (int i = tid; i < OUTD; i += blockDim.x) bl[i] = b_lin[i];
    __syncthreads();

    int lane = tid & 31;
    int wib  = tid >> 5;
    float wl[4][Hh], bb[4];
    #pragma unroll
    for (int c = 0; c < 4; c++) {
        int o = 4 * lane + c;
        bb[c] = bl[o];
        #pragma unroll
        for (int k = 0; k < Hh; k++) wl[c][k] = Wl[o * Hh + k];
    }

    int wpb = blockDim.x >> 5;
    int gw  = blockIdx.x * wpb + wib;
    int nw  = gridDim.x * wpb;
    for (int row = gw; row < BT; row += nw) {
        float v = g_out2[(size_t)row * Hh + (lane < Hh ? lane : 0)];
        float hk[Hh];
        #pragma unroll
        for (int k = 0; k < Hh; k++) hk[k] = __shfl_sync(FULL, v, k);

        float acc[4];
        #pragma unroll
        for (int c = 0; c < 4; c++) {
            acc[c] = bb[c];
            #pragma unroll
            for (int k = 0; k < Hh; k++) acc[c] = fmaf(hk[k], wl[c][k], acc[c]);
        }
        float m = fmaxf(fmaxf(acc[0], acc[1]), fmaxf(acc[2], acc[3]));
        #pragma unroll
        for (int s = 16; s > 0; s >>= 1)
            m = fmaxf(m, __shfl_xor_sync(FULL, m, s));
        float e0 = __expf(acc[0] - m), e1 = __expf(acc[1] - m);
        float e2 = __expf(acc[2] - m), e3 = __expf(acc[3] - m);
        float s = e0 + e1 + e2 + e3;
        #pragma unroll
        for (int sh = 16; sh > 0; sh >>= 1)
            s += __shfl_xor_sync(FULL, s, sh);
        float r = __frcp_rn(s);
        float4 res = make_float4(e0 * r, e1 * r, e2 * r, e3 * r);
        ((float4*)(out + (size_t)row * OUTD))[lane] = res;
    }
}

// ---------------------------------------------------------------------------
extern "C" void kernel_launch(void* const* d_in, const int* in_sizes, int n_in,
                              void* d_out, int out_size)
{
    const float* x      = (const float*)d_in[0];
    const float* W_ih0  = (const float*)d_in[1];
    const float* W_hh0  = (const float*)d_in[2];
    const float* b_ih0  = (const float*)d_in[3];
    const float* b_hh0  = (const float*)d_in[4];
    const float* W_ih1  = (const float*)d_in[5];
    const float* W_hh1  = (const float*)d_in[6];
    const float* b_ih1  = (const float*)d_in[7];
    const float* b_hh1  = (const float*)d_in[8];
    const float* W_lin  = (const float*)d_in[9];
    const float* b_lin  = (const float*)d_in[10];
    float* out = (float*)d_out;

    const int k2_smem = 2 * Tt * 12 * sizeof(float);   // 96KB, 2 batches/block
    cudaFuncSetAttribute(k2_scan, cudaFuncAttributeMaxDynamicSharedMemorySize,
                         k2_smem);

    k1_inproj<<<2048, 128>>>(x, W_ih0, b_ih0, b_hh0);
    k2_scan<<<Bb / 2, 128, k2_smem>>>(W_hh0, W_ih1, W_hh1, b_ih1, b_hh1, out);
    k3_head<<<2048, 256>>>(W_lin, b_lin, out);
}

// round 15
// speedup vs baseline: 1.1995x; 1.0070x over previous
#include <cuda_runtime.h>
#include <cuda_bf16.h>

#define Bb 256
#define Tt 1024
#define INF 128
#define Hh 10
#define OUTD 128
#define BT (Bb*Tt)

// Scratch (no cudaMalloc allowed): device globals
__device__ float g_xp0[(size_t)BT * Hh];   // [BT][10]
__device__ float g_out2[(size_t)BT * Hh];  // [BT][10]

// ---------------------------------------------------------------------------
// Kernel 1: xp0 = x @ W_ih0^T + b. 128-row tile, 256 THREADS: threads
// (r, r+128) split row r's 128 f-values in halves -> per-warp work halves,
// warps/SM 12 -> 24 (occ 2x) at the same 72KB smem. Partial sums combined
// through a 6KB smem pass (xs reused), then packed coalesced STG.128.
// ---------------------------------------------------------------------------
__global__ __launch_bounds__(256) void k1_inproj(
    const float* __restrict__ x,
    const float* __restrict__ W_ih0,
    const float* __restrict__ b_ih0,
    const float* __restrict__ b_hh0)
{
    __shared__ float xs[128 * 129];
    __shared__ float4 Wq[128][3];
    __shared__ float bs[16];
    int tid = threadIdx.x;
    for (int i = tid; i < 128 * 3; i += 256) {
        int f = i / 3, g = i % 3;
        float4 v;
        v.x = (4*g+0 < Hh) ? W_ih0[(4*g+0)*128 + f] : 0.f;
        v.y = (4*g+1 < Hh) ? W_ih0[(4*g+1)*128 + f] : 0.f;
        v.z = (4*g+2 < Hh) ? W_ih0[(4*g+2)*128 + f] : 0.f;
        v.w = (4*g+3 < Hh) ? W_ih0[(4*g+3)*128 + f] : 0.f;
        Wq[f][g] = v;
    }
    if (tid < Hh) bs[tid] = b_ih0[tid] + b_hh0[tid];

    const float* xrow = x + (size_t)blockIdx.x * 128 * 128;
    #pragma unroll 8
    for (int i = tid; i < 128 * 128; i += 256) {
        xs[(i >> 7) * 129 + (i & 127)] = xrow[i];
    }
    __syncthreads();

    int row  = tid & 127;
    int half = tid >> 7;                     // 0: f in [0,64), 1: f in [64,128)
    float acc[Hh];
    #pragma unroll
    for (int h = 0; h < Hh; h++) acc[h] = half ? 0.f : bs[h];

    const float* xr = xs + row * 129 + half * 64;
    #pragma unroll 8
    for (int q = 0; q < 64; q++) {
        int f = half * 64 + q;
        float xv = xr[q];
        float4 wa = Wq[f][0], wb = Wq[f][1], wc = Wq[f][2];
        acc[0] = fmaf(xv, wa.x, acc[0]);
        acc[1] = fmaf(xv, wa.y, acc[1]);
        acc[2] = fmaf(xv, wa.z, acc[2]);
        acc[3] = fmaf(xv, wa.w, acc[3]);
        acc[4] = fmaf(xv, wb.x, acc[4]);
        acc[5] = fmaf(xv, wb.y, acc[5]);
        acc[6] = fmaf(xv, wb.z, acc[6]);
        acc[7] = fmaf(xv, wb.w, acc[7]);
        acc[8] = fmaf(xv, wc.x, acc[8]);
        acc[9] = fmaf(xv, wc.y, acc[9]);
    }

    // Combine halves: half0 writes, half1 adds (one owner per row per phase).
    __syncthreads();                         // all xs reads done
    float* os = xs;                          // reuse as [128][12]
    if (half == 0) {
        #pragma unroll
        for (int h = 0; h < Hh; h++) os[row * 12 + h] = acc[h];
    }
    __syncthreads();
    if (half == 1) {
        #pragma unroll
        for (int h = 0; h < Hh; h++) os[row * 12 + h] += acc[h];
    }
    __syncthreads();

    float4* g4 = (float4*)(g_xp0 + (size_t)blockIdx.x * 128 * Hh); // 1280 floats
    for (int i = tid; i < 320; i += 256) {
        int e = i * 4;
        float4 v;
        v.x = os[(e    ) / 10 * 12 + (e    ) % 10];
        v.y = os[(e + 1) / 10 * 12 + (e + 1) % 10];
        v.z = os[(e + 2) / 10 * 12 + (e + 2) % 10];
        v.w = os[(e + 3) / 10 * 12 + (e + 3) % 10];
        g4[i] = v;
    }
}

// ---------------------------------------------------------------------------
// Kernel 2: warp-specialized scan (R14 proven best, frozen):
//   wid0 = producer(batchA) SMSP0   wid1 = consumer(batchA) SMSP1
//   wid2 = producer(batchB) SMSP2   wid3 = consumer(batchB) SMSP3
// ---------------------------------------------------------------------------
__global__ __launch_bounds__(128) void k2_scan(
    const float* __restrict__ W_hh0,
    const float* __restrict__ W_ih1,
    const float* __restrict__ W_hh1,
    const float* __restrict__ b_ih1,
    const float* __restrict__ b_hh1,
    float* __restrict__ dout)
{
    extern __shared__ float smem[];         // bufA[1024][12] ++ bufB[1024][12]
    __shared__ int prog_s[2];
    const unsigned FULL = 0xffffffffu;
    int tid  = threadIdx.x;
    int wid  = tid >> 5;
    int lane = tid & 31;
    int j    = lane < Hh ? lane : Hh - 1;

    if (tid < 2) prog_s[tid] = 0;
    __syncthreads();

    int side   = wid >> 1;                  // 0 = batch A, 1 = batch B
    int role   = wid & 1;                   // 0 = producer, 1 = consumer
    int batch  = blockIdx.x * 2 + side;
    float* buf = smem + side * (Tt * 12);
    volatile int* pprog = &prog_s[side];

    float* hid = dout + (size_t)BT * OUTD;  // hidden: [2][B][H]

    if (role == 0) {
        float w0r[Hh];
        #pragma unroll
        for (int k = 0; k < Hh; k++) w0r[k] = W_hh0[j * Hh + k];

        const float* xp = g_xp0 + (size_t)batch * Tt * Hh;
        float v0[Hh];
        #pragma unroll
        for (int k = 0; k < Hh; k++) v0[k] = 0.f;

        float xa[8], xb[8];
        #pragma unroll
        for (int d = 0; d < 8; d++) xa[d] = xp[d * Hh + j];

        float h0n = 0.f;
        for (int tb = 0; tb < Tt; tb += 8) {
            if (tb + 8 < Tt) {
                #pragma unroll
                for (int d = 0; d < 8; d++) xb[d] = xp[(tb + 8 + d) * Hh + j];
            }
            #pragma unroll
            for (int d = 0; d < 8; d++) {
                float a0 = xa[d], a1 = 0.f, a2 = 0.f, a3 = 0.f;
                a0 = fmaf(w0r[0], v0[0], a0);
                a1 = fmaf(w0r[1], v0[1], a1);
                a2 = fmaf(w0r[2], v0[2], a2);
                a3 = fmaf(w0r[3], v0[3], a3);
                a0 = fmaf(w0r[4], v0[4], a0);
                a1 = fmaf(w0r[5], v0[5], a1);
                a2 = fmaf(w0r[6], v0[6], a2);
                a3 = fmaf(w0r[7], v0[7], a3);
                a0 = fmaf(w0r[8], v0[8], a0);
                a1 = fmaf(w0r[9], v0[9], a1);
                h0n = fmaxf((a0 + a1) + (a2 + a3), 0.f);
                if (lane < Hh) buf[(tb + d) * 12 + lane] = h0n;
                #pragma unroll
                for (int k = 0; k < Hh; k++) v0[k] = __shfl_sync(FULL, h0n, k);
            }
            __threadfence_block();
            if (lane == 0) *pprog = tb + 8;
            #pragma unroll
            for (int d = 0; d < 8; d++) xa[d] = xb[d];
        }
        if (lane < Hh) hid[batch * Hh + lane] = h0n;      // h0[T-1]
    } else {
        float wi1r[Hh], w1r[Hh];
        #pragma unroll
        for (int k = 0; k < Hh; k++) {
            wi1r[k] = W_ih1[j * Hh + k];
            w1r[k]  = W_hh1[j * Hh + k];
        }
        float bias1 = b_ih1[j] + b_hh1[j];
        float* o2 = g_out2 + (size_t)batch * Tt * Hh;

        float v1[Hh];
        #pragma unroll
        for (int k = 0; k < Hh; k++) v1[k] = 0.f;
        float h1n = 0.f;

        int seen = 0;
        while ((seen = *pprog) < 8) { }
        __threadfence_block();
        const float4* rb = (const float4*)buf;
        float4 c0 = rb[0], c1 = rb[1], c2 = rb[2];

        for (int tb = 0; tb < Tt; tb += 8) {
            #pragma unroll
            for (int d = 0; d < 8; d++) {
                float4 n0, n1, n2;
                if (d < 7) {
                    const float4* rn = (const float4*)(buf + (tb + d + 1) * 12);
                    n0 = rn[0]; n1 = rn[1]; n2 = rn[2];
                }
                float r0 = bias1, r1 = 0.f, r2 = 0.f, r3 = 0.f;
                r0 = fmaf(wi1r[0], c0.x, r0);
                r1 = fmaf(wi1r[1], c0.y, r1);
                r2 = fmaf(wi1r[2], c0.z, r2);
                r3 = fmaf(wi1r[3], c0.w, r3);
                r0 = fmaf(wi1r[4], c1.x, r0);
                r1 = fmaf(wi1r[5], c1.y, r1);
                r2 = fmaf(wi1r[6], c1.z, r2);
                r3 = fmaf(wi1r[7], c1.w, r3);
                r0 = fmaf(wi1r[8], c2.x, r0);
                r1 = fmaf(wi1r[9], c2.y, r1);
                r0 = fmaf(w1r[0], v1[0], r0);
                r1 = fmaf(w1r[1], v1[1], r1);
                r2 = fmaf(w1r[2], v1[2], r2);
                r3 = fmaf(w1r[3], v1[3], r3);
                r0 = fmaf(w1r[4], v1[4], r0);
                r1 = fmaf(w1r[5], v1[5], r1);
                r2 = fmaf(w1r[6], v1[6], r2);
                r3 = fmaf(w1r[7], v1[7], r3);
                r0 = fmaf(w1r[8], v1[8], r0);
                r1 = fmaf(w1r[9], v1[9], r1);
                h1n = fmaxf((r0 + r1) + (r2 + r3), 0.f);
                if (lane < Hh) o2[(size_t)(tb + d) * Hh + lane] = h1n;
                #pragma unroll
                for (int k = 0; k < Hh; k++) v1[k] = __shfl_sync(FULL, h1n, k);
                if (d < 7) { c0 = n0; c1 = n1; c2 = n2; }
            }
            if (tb + 8 < Tt) {
                int need = tb + 16;
                if (seen < need) {
                    while ((seen = *pprog) < need) { }
                    __threadfence_block();
                }
                const float4* rn = (const float4*)(buf + (tb + 8) * 12);
                c0 = rn[0]; c1 = rn[1]; c2 = rn[2];
            }
        }
        if (lane < Hh) hid[Bb * Hh + batch * Hh + lane] = h1n;   // h1[T-1]
    }
}

// ---------------------------------------------------------------------------
// Kernel 3: logits = out2 @ W_lin^T + b_lin, softmax over 128. (frozen R6)
// ---------------------------------------------------------------------------
__global__ __launch_bounds__(256) void k3_head(
    const float* __restrict__ W_lin,
    const float* __restrict__ b_lin,
    float* __restrict__ out)
{
    const unsigned FULL = 0xffffffffu;
    __shared__ float Wl[OUTD * Hh];
    __shared__ float bl[OUTD];
    int tid = threadIdx.x;
    for (int i = tid; i < OUTD * Hh; i += blockDim.x) Wl[i] = W_lin[i];
    for (int i = tid; i < OUTD; i += blockDim.x) bl[i] = b_lin[i];
    __syncthreads();

    int lane = tid & 31;
    int wib  = tid >> 5;
    float wl[4][Hh], bb[4];
    #pragma unroll
    for (int c = 0; c < 4; c++) {
        int o = 4 * lane + c;
        bb[c] = bl[o];
        #pragma unroll
        for (int k = 0; k < Hh; k++) wl[c][k] = Wl[o * Hh + k];
    }

    int wpb = blockDim.x >> 5;
    int gw  = blockIdx.x * wpb + wib;
    int nw  = gridDim.x * wpb;
    for (int row = gw; row < BT; row += nw) {
        float v = g_out2[(size_t)row * Hh + (lane < Hh ? lane : 0)];
        float hk[Hh];
        #pragma unroll
        for (int k = 0; k < Hh; k++) hk[k] = __shfl_sync(FULL, v, k);

        float acc[4];
        #pragma unroll
        for (int c = 0; c < 4; c++) {
            acc[c] = bb[c];
            #pragma unroll
            for (int k = 0; k < Hh; k++) acc[c] = fmaf(hk[k], wl[c][k], acc[c]);
        }
        float m = fmaxf(fmaxf(acc[0], acc[1]), fmaxf(acc[2], acc[3]));
        #pragma unroll
        for (int s = 16; s > 0; s >>= 1)
            m = fmaxf(m, __shfl_xor_sync(FULL, m, s));
        float e0 = __expf(acc[0] - m), e1 = __expf(acc[1] - m);
        float e2 = __expf(acc[2] - m), e3 = __expf(acc[3] - m);
        float s = e0 + e1 + e2 + e3;
        #pragma unroll
        for (int sh = 16; sh > 0; sh >>= 1)
            s += __shfl_xor_sync(FULL, s, sh);
        float r = __frcp_rn(s);
        float4 res = make_float4(e0 * r, e1 * r, e2 * r, e3 * r);
        ((float4*)(out + (size_t)row * OUTD))[lane] = res;
    }
}

// ---------------------------------------------------------------------------
extern "C" void kernel_launch(void* const* d_in, const int* in_sizes, int n_in,
                              void* d_out, int out_size)
{
    const float* x      = (const float*)d_in[0];
    const float* W_ih0  = (const float*)d_in[1];
    const float* W_hh0  = (const float*)d_in[2];
    const float* b_ih0  = (const float*)d_in[3];
    const float* b_hh0  = (const float*)d_in[4];
    const float* W_ih1  = (const float*)d_in[5];
    const float* W_hh1  = (const float*)d_in[6];
    const float* b_ih1  = (const float*)d_in[7];
    const float* b_hh1  = (const float*)d_in[8];
    const float* W_lin  = (const float*)d_in[9];
    const float* b_lin  = (const float*)d_in[10];
    float* out = (float*)d_out;

    const int k2_smem = 2 * Tt * 12 * sizeof(float);   // 96KB, 2 batches/block
    cudaFuncSetAttribute(k2_scan, cudaFuncAttributeMaxDynamicSharedMemorySize,
                         k2_smem);

    k1_inproj<<<2048, 256>>>(x, W_ih0, b_ih0, b_hh0);
    k2_scan<<<Bb / 2, 128, k2_smem>>>(W_hh0, W_ih1, W_hh1, b_ih1, b_hh1, out);
    k3_head<<<2048, 256>>>(W_lin, b_lin, out);
}